// round 1
// baseline (speedup 1.0000x reference)
#include <cuda_runtime.h>

#define NATOMS 1024
#define NBATCH 32
#define TPB    256
#define CHUNKS 4   // i-chunks per batch -> grid = 32*4 = 128 blocks (one wave on 148 SMs)

__global__ void lj_zero_energy(float* __restrict__ out) {
    if (threadIdx.x < NBATCH) out[threadIdx.x] = 0.0f;
}

__global__ __launch_bounds__(TPB) void lj_kernel(const float* __restrict__ pos,
                                                 float* __restrict__ out) {
    __shared__ float4 sp[NATOMS];          // positions of this block's batch
    __shared__ float  wred[8 * 3];         // warp partials for mean
    __shared__ float  ered[8];             // warp partials for energy

    const int b     = blockIdx.x / CHUNKS;
    const int chunk = blockIdx.x % CHUNKS;
    const int tid   = threadIdx.x;
    const int lane  = tid & 31;
    const int warp  = tid >> 5;

    const float* __restrict__ p = pos + (size_t)b * NATOMS * 3;

    // Stage full batch into shared as float4 (w unused)
    for (int a = tid; a < NATOMS; a += TPB) {
        sp[a] = make_float4(p[3 * a + 0], p[3 * a + 1], p[3 * a + 2], 0.0f);
    }
    __syncthreads();

    // ---- batch mean (block-wide reduction over shared) ----
    float mx = 0.0f, my = 0.0f, mz = 0.0f;
    for (int a = tid; a < NATOMS; a += TPB) {
        float4 q = sp[a];
        mx += q.x; my += q.y; mz += q.z;
    }
    #pragma unroll
    for (int o = 16; o > 0; o >>= 1) {
        mx += __shfl_xor_sync(0xFFFFFFFFu, mx, o);
        my += __shfl_xor_sync(0xFFFFFFFFu, my, o);
        mz += __shfl_xor_sync(0xFFFFFFFFu, mz, o);
    }
    if (lane == 0) {
        wred[warp * 3 + 0] = mx;
        wred[warp * 3 + 1] = my;
        wred[warp * 3 + 2] = mz;
    }
    __syncthreads();
    mx = 0.0f; my = 0.0f; mz = 0.0f;
    #pragma unroll
    for (int k = 0; k < 8; k++) {
        mx += wred[k * 3 + 0];
        my += wred[k * 3 + 1];
        mz += wred[k * 3 + 2];
    }
    const float inv_n = 1.0f / (float)NATOMS;
    mx *= inv_n; my *= inv_n; mz *= inv_n;

    // ---- pair loop: this thread owns atom i ----
    const int i = chunk * TPB + tid;
    const float4 pi = sp[i];
    const float xi = pi.x, yi = pi.y, zi = pi.z;

    float e  = 0.0f;
    float fx = 0.0f, fy = 0.0f, fz = 0.0f;

    #pragma unroll 8
    for (int j = 0; j < NATOMS; j++) {
        float4 pj = sp[j];                        // LDS.128 broadcast
        float dx = xi - pj.x;
        float dy = yi - pj.y;
        float dz = zi - pj.z;
        float sq = fmaf(dx, dx, fmaf(dy, dy, dz * dz));
        sq = (j == i) ? 3.0e38f : sq;             // self-pair -> invsq underflows to 0
        float invsq = __fdividef(1.0f, sq);
        float inv6  = invsq * invsq * invsq;
        float inv12 = inv6 * inv6;
        e += fmaf(-2.0f, inv6, inv12);            // r^-12 - 2 r^-6
        float c = (inv12 - inv6) * invsq;         // fold *12 after the loop
        fx = fmaf(c, dx, fx);
        fy = fmaf(c, dy, fy);
        fz = fmaf(c, dz, fz);
    }

    e  *= 0.5f;                                   // each pair counted twice
    fx *= 12.0f; fy *= 12.0f; fz *= 12.0f;

    // oscillator term
    const float xcx = xi - mx, xcy = yi - my, xcz = zi - mz;
    e  += 0.125f * fmaf(xcx, xcx, fmaf(xcy, xcy, xcz * xcz));  // 0.25 * 0.5 * |xc|^2
    fx -= 0.25f * xcx;
    fy -= 0.25f * xcy;
    fz -= 0.25f * xcz;

    // forces (tau = 1): out layout = energy[32] ++ forces[B*N*3]
    float* __restrict__ f = out + NBATCH + (size_t)(b * NATOMS + i) * 3;
    f[0] = fx; f[1] = fy; f[2] = fz;

    // ---- energy reduction: warp shuffles -> shared -> one atomicAdd per block ----
    #pragma unroll
    for (int o = 16; o > 0; o >>= 1)
        e += __shfl_xor_sync(0xFFFFFFFFu, e, o);
    if (lane == 0) ered[warp] = e;
    __syncthreads();
    if (tid == 0) {
        float esum = 0.0f;
        #pragma unroll
        for (int k = 0; k < 8; k++) esum += ered[k];
        atomicAdd(out + b, esum);
    }
}

extern "C" void kernel_launch(void* const* d_in, const int* in_sizes, int n_in,
                              void* d_out, int out_size) {
    const float* pos = (const float*)d_in[0];
    float* out = (float*)d_out;
    lj_zero_energy<<<1, 32>>>(out);
    lj_kernel<<<NBATCH * CHUNKS, TPB>>>(pos, out);
}

// round 2
// speedup vs baseline: 1.5760x; 1.5760x over previous
#include <cuda_runtime.h>

#define NATOMS 1024
#define NBATCH 32
#define TPB    256
#define CHUNKS 4                 // i-chunks per batch (256 atoms each)
#define JSPLIT 4                 // j-quarters per i-chunk
#define JTILE  (NATOMS / JSPLIT) // 256
// grid = NBATCH * CHUNKS * JSPLIT = 512 blocks

__global__ void lj_zero_out(float* __restrict__ out, int n) {
    int idx = blockIdx.x * blockDim.x + threadIdx.x;
    for (; idx < n; idx += gridDim.x * blockDim.x) out[idx] = 0.0f;
}

__global__ __launch_bounds__(TPB) void lj_kernel(const float* __restrict__ pos,
                                                 float* __restrict__ out) {
    __shared__ float4 sj[JTILE];       // this block's j-tile
    __shared__ float  wred[8 * 3];
    __shared__ float  ered[8];

    const int bi    = blockIdx.x;
    const int b     = bi >> 4;         // / (CHUNKS*JSPLIT)
    const int chunk = (bi >> 2) & 3;
    const int jpart = bi & 3;
    const int tid   = threadIdx.x;
    const int lane  = tid & 31;
    const int warp  = tid >> 5;

    const float* __restrict__ p = pos + (size_t)b * NATOMS * 3;

    // stage j-tile (TPB == JTILE: one atom per thread)
    {
        const int ja = jpart * JTILE + tid;
        sj[tid] = make_float4(p[3 * ja + 0], p[3 * ja + 1], p[3 * ja + 2], 0.0f);
    }

    // own i-atom from global
    const int i  = chunk * TPB + tid;
    const float xi = p[3 * i + 0];
    const float yi = p[3 * i + 1];
    const float zi = p[3 * i + 2];
    __syncthreads();

    const int ii = i - jpart * JTILE;  // self-index within tile (may be out of range)

    float e  = 0.0f;
    float fx = 0.0f, fy = 0.0f, fz = 0.0f;

    #pragma unroll 8
    for (int jj = 0; jj < JTILE; jj++) {
        float4 pj = sj[jj];                       // LDS.128 broadcast
        float dx = xi - pj.x;
        float dy = yi - pj.y;
        float dz = zi - pj.z;
        float sq = fmaf(dx, dx, fmaf(dy, dy, dz * dz));
        sq = (jj == ii) ? 3.0e38f : sq;           // self-pair: rcp underflows to 0
        float invsq = __fdividef(1.0f, sq);       // MUFU.RCP
        float inv6  = invsq * invsq * invsq;
        float inv12 = inv6 * inv6;
        e += fmaf(-2.0f, inv6, inv12);
        float c = (inv12 - inv6) * invsq;         // fold *12 after loop
        fx = fmaf(c, dx, fx);
        fy = fmaf(c, dy, fy);
        fz = fmaf(c, dz, fz);
    }

    e  *= 0.5f;
    fx *= 12.0f; fy *= 12.0f; fz *= 12.0f;

    // oscillator term: only the jpart==0 block adds it (once per i)
    if (jpart == 0) {
        float mx = 0.0f, my = 0.0f, mz = 0.0f;
        for (int a = tid; a < NATOMS; a += TPB) {
            mx += p[3 * a + 0];
            my += p[3 * a + 1];
            mz += p[3 * a + 2];
        }
        #pragma unroll
        for (int o = 16; o > 0; o >>= 1) {
            mx += __shfl_xor_sync(0xFFFFFFFFu, mx, o);
            my += __shfl_xor_sync(0xFFFFFFFFu, my, o);
            mz += __shfl_xor_sync(0xFFFFFFFFu, mz, o);
        }
        if (lane == 0) {
            wred[warp * 3 + 0] = mx;
            wred[warp * 3 + 1] = my;
            wred[warp * 3 + 2] = mz;
        }
        __syncthreads();
        mx = 0.0f; my = 0.0f; mz = 0.0f;
        #pragma unroll
        for (int k = 0; k < 8; k++) {
            mx += wred[k * 3 + 0];
            my += wred[k * 3 + 1];
            mz += wred[k * 3 + 2];
        }
        const float inv_n = 1.0f / (float)NATOMS;
        mx *= inv_n; my *= inv_n; mz *= inv_n;

        const float xcx = xi - mx, xcy = yi - my, xcz = zi - mz;
        e  += 0.125f * fmaf(xcx, xcx, fmaf(xcy, xcy, xcz * xcz));
        fx -= 0.25f * xcx;
        fy -= 0.25f * xcy;
        fz -= 0.25f * xcz;
    }

    // partial forces: atomicAdd into zero-initialized output (REDG, spread addrs)
    float* __restrict__ f = out + NBATCH + (size_t)(b * NATOMS + i) * 3;
    atomicAdd(f + 0, fx);
    atomicAdd(f + 1, fy);
    atomicAdd(f + 2, fz);

    // energy partial: warp shuffles -> shared -> one atomicAdd per block
    #pragma unroll
    for (int o = 16; o > 0; o >>= 1)
        e += __shfl_xor_sync(0xFFFFFFFFu, e, o);
    if (lane == 0) ered[warp] = e;
    __syncthreads();
    if (tid == 0) {
        float esum = 0.0f;
        #pragma unroll
        for (int k = 0; k < 8; k++) esum += ered[k];
        atomicAdd(out + b, esum);
    }
}

extern "C" void kernel_launch(void* const* d_in, const int* in_sizes, int n_in,
                              void* d_out, int out_size) {
    const float* pos = (const float*)d_in[0];
    float* out = (float*)d_out;
    lj_zero_out<<<148, TPB>>>(out, out_size);
    lj_kernel<<<NBATCH * CHUNKS * JSPLIT, TPB>>>(pos, out);
}

// round 3
// speedup vs baseline: 1.7677x; 1.1217x over previous
#include <cuda_runtime.h>

#define NATOMS 1024
#define NBATCH 32
#define TPB    256
#define CHUNKS 4                 // i-chunks per batch (256 atoms each)
#define JSPLIT 4                 // j-quarters per i-chunk
#define JTILE  (NATOMS / JSPLIT) // 256
#define JPAIRS (JTILE / 2)       // 128 packed pairs

typedef unsigned long long ull;

__device__ __forceinline__ ull f2pack(float lo, float hi) {
    ull r;
    asm("mov.b64 %0, {%1, %2};" : "=l"(r)
        : "r"(__float_as_uint(lo)), "r"(__float_as_uint(hi)));
    return r;
}
__device__ __forceinline__ void f2unpack(ull v, float& lo, float& hi) {
    unsigned a, b;
    asm("mov.b64 {%0, %1}, %2;" : "=r"(a), "=r"(b) : "l"(v));
    lo = __uint_as_float(a);
    hi = __uint_as_float(b);
}
__device__ __forceinline__ ull f2add(ull a, ull b) {
    ull r; asm("add.rn.f32x2 %0, %1, %2;" : "=l"(r) : "l"(a), "l"(b)); return r;
}
__device__ __forceinline__ ull f2mul(ull a, ull b) {
    ull r; asm("mul.rn.f32x2 %0, %1, %2;" : "=l"(r) : "l"(a), "l"(b)); return r;
}
__device__ __forceinline__ ull f2fma(ull a, ull b, ull c) {
    ull r; asm("fma.rn.f32x2 %0, %1, %2, %3;" : "=l"(r) : "l"(a), "l"(b), "l"(c)); return r;
}

__global__ void lj_zero_out(float* __restrict__ out, int n) {
    int idx = blockIdx.x * blockDim.x + threadIdx.x;
    for (; idx < n; idx += gridDim.x * blockDim.x) out[idx] = 0.0f;
}

// Inner pair loop over the packed shared tile. SELF: tile contains thread's own atom.
template <bool SELF>
__device__ __forceinline__ void pair_loop(
    const float4* __restrict__ sxy, const float2* __restrict__ sz,
    ull xi2, ull yi2, ull zi2, int m0, int m1,
    ull& fx2, ull& fy2, ull& fz2, ull& a6, ull& a12)
{
    const ull MINUS1 = f2pack(-1.0f, -1.0f);
    #pragma unroll 8
    for (int m = 0; m < JPAIRS; m++) {
        float4 q  = sxy[m];                 // (-x0,-x1,-y0,-y1)  LDS.128 broadcast
        float2 zz = sz[m];                  // (-z0,-z1)          LDS.64  broadcast
        ull nx2 = f2pack(q.x, q.y);
        ull ny2 = f2pack(q.z, q.w);
        ull nz2 = f2pack(zz.x, zz.y);

        ull dx2 = f2add(xi2, nx2);
        ull dy2 = f2add(yi2, ny2);
        ull dz2 = f2add(zi2, nz2);
        ull sq2 = f2mul(dx2, dx2);
        sq2 = f2fma(dy2, dy2, sq2);
        sq2 = f2fma(dz2, dz2, sq2);

        float s0, s1;
        f2unpack(sq2, s0, s1);
        if (SELF) {                         // self-pair -> rcp underflows to 0
            s0 = (m == m0) ? 3.0e38f : s0;
            s1 = (m == m1) ? 3.0e38f : s1;
        }
        float r0 = __fdividef(1.0f, s0);    // MUFU.RCP
        float r1 = __fdividef(1.0f, s1);
        ull invsq2 = f2pack(r0, r1);

        ull t4   = f2mul(invsq2, invsq2);
        ull inv6 = f2mul(t4, invsq2);
        ull inv12 = f2mul(inv6, inv6);
        a6  = f2add(a6, inv6);
        a12 = f2add(a12, inv12);
        ull diff = f2fma(inv6, MINUS1, inv12);   // inv12 - inv6
        ull c2   = f2mul(diff, invsq2);
        fx2 = f2fma(c2, dx2, fx2);
        fy2 = f2fma(c2, dy2, fy2);
        fz2 = f2fma(c2, dz2, fz2);
    }
}

__global__ __launch_bounds__(TPB) void lj_kernel(const float* __restrict__ pos,
                                                 float* __restrict__ out) {
    __shared__ float4 sxy[JPAIRS];
    __shared__ float2 sz[JPAIRS];
    __shared__ float  wred[8 * 3];
    __shared__ float  ered[8];

    const int bi    = blockIdx.x;
    const int b     = bi >> 4;
    const int chunk = (bi >> 2) & 3;
    const int jpart = bi & 3;
    const int tid   = threadIdx.x;
    const int lane  = tid & 31;
    const int warp  = tid >> 5;

    const float* __restrict__ p = pos + (size_t)b * NATOMS * 3;

    // stage packed, negated j-tile: pair m -> atoms (2m, 2m+1) of this quarter
    if (tid < JPAIRS) {
        const int j0 = jpart * JTILE + 2 * tid;
        float x0 = p[3 * j0 + 0], y0 = p[3 * j0 + 1], z0 = p[3 * j0 + 2];
        float x1 = p[3 * j0 + 3], y1 = p[3 * j0 + 4], z1 = p[3 * j0 + 5];
        sxy[tid] = make_float4(-x0, -x1, -y0, -y1);
        sz[tid]  = make_float2(-z0, -z1);
    }

    const int i  = chunk * TPB + tid;
    const float xi = p[3 * i + 0];
    const float yi = p[3 * i + 1];
    const float zi = p[3 * i + 2];
    __syncthreads();

    const ull xi2 = f2pack(xi, xi);
    const ull yi2 = f2pack(yi, yi);
    const ull zi2 = f2pack(zi, zi);

    ull fx2 = 0, fy2 = 0, fz2 = 0, a6 = 0, a12 = 0;  // 0ull == packed {0.f,0.f}

    if (chunk == jpart) {
        const int ii = i - jpart * JTILE;            // in [0, JTILE)
        const int m0 = ((ii & 1) == 0) ? (ii >> 1) : -1;
        const int m1 = ((ii & 1) == 1) ? (ii >> 1) : -1;
        pair_loop<true>(sxy, sz, xi2, yi2, zi2, m0, m1, fx2, fy2, fz2, a6, a12);
    } else {
        pair_loop<false>(sxy, sz, xi2, yi2, zi2, -1, -1, fx2, fy2, fz2, a6, a12);
    }

    float fxl, fxh, fyl, fyh, fzl, fzh, a6l, a6h, a12l, a12h;
    f2unpack(fx2, fxl, fxh);
    f2unpack(fy2, fyl, fyh);
    f2unpack(fz2, fzl, fzh);
    f2unpack(a6, a6l, a6h);
    f2unpack(a12, a12l, a12h);

    float e  = 0.5f * ((a12l + a12h) - 2.0f * (a6l + a6h));
    float fx = 12.0f * (fxl + fxh);
    float fy = 12.0f * (fyl + fyh);
    float fz = 12.0f * (fzl + fzh);

    // oscillator term: only the jpart==0 block adds it (once per i)
    if (jpart == 0) {
        float mx = 0.0f, my = 0.0f, mz = 0.0f;
        for (int a = tid; a < NATOMS; a += TPB) {
            mx += p[3 * a + 0];
            my += p[3 * a + 1];
            mz += p[3 * a + 2];
        }
        #pragma unroll
        for (int o = 16; o > 0; o >>= 1) {
            mx += __shfl_xor_sync(0xFFFFFFFFu, mx, o);
            my += __shfl_xor_sync(0xFFFFFFFFu, my, o);
            mz += __shfl_xor_sync(0xFFFFFFFFu, mz, o);
        }
        if (lane == 0) {
            wred[warp * 3 + 0] = mx;
            wred[warp * 3 + 1] = my;
            wred[warp * 3 + 2] = mz;
        }
        __syncthreads();
        mx = 0.0f; my = 0.0f; mz = 0.0f;
        #pragma unroll
        for (int k = 0; k < 8; k++) {
            mx += wred[k * 3 + 0];
            my += wred[k * 3 + 1];
            mz += wred[k * 3 + 2];
        }
        const float inv_n = 1.0f / (float)NATOMS;
        mx *= inv_n; my *= inv_n; mz *= inv_n;

        const float xcx = xi - mx, xcy = yi - my, xcz = zi - mz;
        e  += 0.125f * fmaf(xcx, xcx, fmaf(xcy, xcy, xcz * xcz));
        fx -= 0.25f * xcx;
        fy -= 0.25f * xcy;
        fz -= 0.25f * xcz;
    }

    // partial forces into zero-initialized output (REDG, spread addresses)
    float* __restrict__ f = out + NBATCH + (size_t)(b * NATOMS + i) * 3;
    atomicAdd(f + 0, fx);
    atomicAdd(f + 1, fy);
    atomicAdd(f + 2, fz);

    // energy partial: warp shuffles -> shared -> one atomicAdd per block
    #pragma unroll
    for (int o = 16; o > 0; o >>= 1)
        e += __shfl_xor_sync(0xFFFFFFFFu, e, o);
    if (lane == 0) ered[warp] = e;
    __syncthreads();
    if (tid == 0) {
        float esum = 0.0f;
        #pragma unroll
        for (int k = 0; k < 8; k++) esum += ered[k];
        atomicAdd(out + b, esum);
    }
}

extern "C" void kernel_launch(void* const* d_in, const int* in_sizes, int n_in,
                              void* d_out, int out_size) {
    const float* pos = (const float*)d_in[0];
    float* out = (float*)d_out;
    lj_zero_out<<<148, TPB>>>(out, out_size);
    lj_kernel<<<NBATCH * CHUNKS * JSPLIT, TPB>>>(pos, out);
}

// round 4
// speedup vs baseline: 1.9958x; 1.1290x over previous
#include <cuda_runtime.h>

#define NATOMS 1024
#define NBATCH 32
#define TPB    256
#define CHUNKS 4                 // i-chunks per batch (256 atoms each)
#define JSPLIT 8                 // j-eighths per i-chunk
#define JTILE  (NATOMS / JSPLIT) // 128
#define JPAIRS (JTILE / 2)       // 64 packed pairs
// grid = NBATCH * CHUNKS * JSPLIT = 1024 blocks

typedef unsigned long long ull;

__device__ __forceinline__ ull f2pack(float lo, float hi) {
    ull r;
    asm("mov.b64 %0, {%1, %2};" : "=l"(r)
        : "r"(__float_as_uint(lo)), "r"(__float_as_uint(hi)));
    return r;
}
__device__ __forceinline__ void f2unpack(ull v, float& lo, float& hi) {
    unsigned a, b;
    asm("mov.b64 {%0, %1}, %2;" : "=r"(a), "=r"(b) : "l"(v));
    lo = __uint_as_float(a);
    hi = __uint_as_float(b);
}
__device__ __forceinline__ ull f2add(ull a, ull b) {
    ull r; asm("add.rn.f32x2 %0, %1, %2;" : "=l"(r) : "l"(a), "l"(b)); return r;
}
__device__ __forceinline__ ull f2mul(ull a, ull b) {
    ull r; asm("mul.rn.f32x2 %0, %1, %2;" : "=l"(r) : "l"(a), "l"(b)); return r;
}
__device__ __forceinline__ ull f2fma(ull a, ull b, ull c) {
    ull r; asm("fma.rn.f32x2 %0, %1, %2, %3;" : "=l"(r) : "l"(a), "l"(b), "l"(c)); return r;
}

__global__ void lj_zero_out(float* __restrict__ out, int n) {
    int idx = blockIdx.x * blockDim.x + threadIdx.x;
    for (; idx < n; idx += gridDim.x * blockDim.x) out[idx] = 0.0f;
}

// Inner pair loop over the packed shared tile. SELF: tile may contain thread's own atom.
template <bool SELF>
__device__ __forceinline__ void pair_loop(
    const float4* __restrict__ sxy, const float2* __restrict__ sz,
    ull xi2, ull yi2, ull zi2, int m0, int m1,
    ull& fx2, ull& fy2, ull& fz2, ull& a6, ull& a12)
{
    const ull MINUS1 = f2pack(-1.0f, -1.0f);
    #pragma unroll 8
    for (int m = 0; m < JPAIRS; m++) {
        float4 q  = sxy[m];                 // (-x0,-x1,-y0,-y1)  LDS.128 broadcast
        float2 zz = sz[m];                  // (-z0,-z1)          LDS.64  broadcast
        ull nx2 = f2pack(q.x, q.y);
        ull ny2 = f2pack(q.z, q.w);
        ull nz2 = f2pack(zz.x, zz.y);

        ull dx2 = f2add(xi2, nx2);
        ull dy2 = f2add(yi2, ny2);
        ull dz2 = f2add(zi2, nz2);
        ull sq2 = f2mul(dx2, dx2);
        sq2 = f2fma(dy2, dy2, sq2);
        sq2 = f2fma(dz2, dz2, sq2);

        float s0, s1;
        f2unpack(sq2, s0, s1);
        if (SELF) {                         // self-pair -> rcp underflows to 0
            s0 = (m == m0) ? 3.0e38f : s0;
            s1 = (m == m1) ? 3.0e38f : s1;
        }
        float r0 = __fdividef(1.0f, s0);    // MUFU.RCP
        float r1 = __fdividef(1.0f, s1);
        ull invsq2 = f2pack(r0, r1);

        ull t4    = f2mul(invsq2, invsq2);
        ull inv6  = f2mul(t4, invsq2);
        ull inv12 = f2mul(inv6, inv6);
        a6  = f2add(a6, inv6);
        a12 = f2add(a12, inv12);
        ull diff = f2fma(inv6, MINUS1, inv12);   // inv12 - inv6
        ull c2   = f2mul(diff, invsq2);
        fx2 = f2fma(c2, dx2, fx2);
        fy2 = f2fma(c2, dy2, fy2);
        fz2 = f2fma(c2, dz2, fz2);
    }
}

__global__ __launch_bounds__(TPB, 5) void lj_kernel(const float* __restrict__ pos,
                                                    float* __restrict__ out) {
    __shared__ float4 sxy[JPAIRS];
    __shared__ float2 sz[JPAIRS];
    __shared__ float  wred[8 * 3];
    __shared__ float  ered[8];

    const int bi    = blockIdx.x;
    const int b     = bi >> 5;         // / (CHUNKS*JSPLIT)
    const int chunk = (bi >> 3) & 3;
    const int jpart = bi & 7;
    const int tid   = threadIdx.x;
    const int lane  = tid & 31;
    const int warp  = tid >> 5;

    const float* __restrict__ p = pos + (size_t)b * NATOMS * 3;

    // stage packed, negated j-tile: pair m -> atoms (2m, 2m+1) of this eighth
    if (tid < JPAIRS) {
        const int j0 = jpart * JTILE + 2 * tid;
        float x0 = p[3 * j0 + 0], y0 = p[3 * j0 + 1], z0 = p[3 * j0 + 2];
        float x1 = p[3 * j0 + 3], y1 = p[3 * j0 + 4], z1 = p[3 * j0 + 5];
        sxy[tid] = make_float4(-x0, -x1, -y0, -y1);
        sz[tid]  = make_float2(-z0, -z1);
    }

    const int i  = chunk * TPB + tid;
    const float xi = p[3 * i + 0];
    const float yi = p[3 * i + 1];
    const float zi = p[3 * i + 2];
    __syncthreads();

    const ull xi2 = f2pack(xi, xi);
    const ull yi2 = f2pack(yi, yi);
    const ull zi2 = f2pack(zi, zi);

    ull fx2 = 0, fy2 = 0, fz2 = 0, a6 = 0, a12 = 0;  // 0ull == packed {0.f,0.f}

    if ((jpart >> 1) == chunk) {
        // this j-tile overlaps this i-chunk: thread's own atom may be in the tile
        const int ii = i - jpart * JTILE;            // in [0, JTILE) iff self present
        const bool in = (ii >= 0) && (ii < JTILE);
        const int m0 = (in && ((ii & 1) == 0)) ? (ii >> 1) : -1;
        const int m1 = (in && ((ii & 1) == 1)) ? (ii >> 1) : -1;
        pair_loop<true>(sxy, sz, xi2, yi2, zi2, m0, m1, fx2, fy2, fz2, a6, a12);
    } else {
        pair_loop<false>(sxy, sz, xi2, yi2, zi2, -1, -1, fx2, fy2, fz2, a6, a12);
    }

    float fxl, fxh, fyl, fyh, fzl, fzh, a6l, a6h, a12l, a12h;
    f2unpack(fx2, fxl, fxh);
    f2unpack(fy2, fyl, fyh);
    f2unpack(fz2, fzl, fzh);
    f2unpack(a6, a6l, a6h);
    f2unpack(a12, a12l, a12h);

    float e  = 0.5f * ((a12l + a12h) - 2.0f * (a6l + a6h));
    float fx = 12.0f * (fxl + fxh);
    float fy = 12.0f * (fyl + fyh);
    float fz = 12.0f * (fzl + fzh);

    // oscillator term: only the jpart==0 block adds it (once per i)
    if (jpart == 0) {
        float mx = 0.0f, my = 0.0f, mz = 0.0f;
        for (int a = tid; a < NATOMS; a += TPB) {
            mx += p[3 * a + 0];
            my += p[3 * a + 1];
            mz += p[3 * a + 2];
        }
        #pragma unroll
        for (int o = 16; o > 0; o >>= 1) {
            mx += __shfl_xor_sync(0xFFFFFFFFu, mx, o);
            my += __shfl_xor_sync(0xFFFFFFFFu, my, o);
            mz += __shfl_xor_sync(0xFFFFFFFFu, mz, o);
        }
        if (lane == 0) {
            wred[warp * 3 + 0] = mx;
            wred[warp * 3 + 1] = my;
            wred[warp * 3 + 2] = mz;
        }
        __syncthreads();
        mx = 0.0f; my = 0.0f; mz = 0.0f;
        #pragma unroll
        for (int k = 0; k < 8; k++) {
            mx += wred[k * 3 + 0];
            my += wred[k * 3 + 1];
            mz += wred[k * 3 + 2];
        }
        const float inv_n = 1.0f / (float)NATOMS;
        mx *= inv_n; my *= inv_n; mz *= inv_n;

        const float xcx = xi - mx, xcy = yi - my, xcz = zi - mz;
        e  += 0.125f * fmaf(xcx, xcx, fmaf(xcy, xcy, xcz * xcz));
        fx -= 0.25f * xcx;
        fy -= 0.25f * xcy;
        fz -= 0.25f * xcz;
    }

    // partial forces into zero-initialized output (REDG, spread addresses)
    float* __restrict__ f = out + NBATCH + (size_t)(b * NATOMS + i) * 3;
    atomicAdd(f + 0, fx);
    atomicAdd(f + 1, fy);
    atomicAdd(f + 2, fz);

    // energy partial: warp shuffles -> shared -> one atomicAdd per block
    #pragma unroll
    for (int o = 16; o > 0; o >>= 1)
        e += __shfl_xor_sync(0xFFFFFFFFu, e, o);
    if (lane == 0) ered[warp] = e;
    __syncthreads();
    if (tid == 0) {
        float esum = 0.0f;
        #pragma unroll
        for (int k = 0; k < 8; k++) esum += ered[k];
        atomicAdd(out + b, esum);
    }
}

extern "C" void kernel_launch(void* const* d_in, const int* in_sizes, int n_in,
                              void* d_out, int out_size) {
    const float* pos = (const float*)d_in[0];
    float* out = (float*)d_out;
    lj_zero_out<<<148, TPB>>>(out, out_size);
    lj_kernel<<<NBATCH * CHUNKS * JSPLIT, TPB>>>(pos, out);
}